// round 2
// baseline (speedup 1.0000x reference)
#include <cuda_runtime.h>

// BasicRNN: B=128, S=8000, H=64. One block per batch (128 blocks ~ 1 per SM).
// 4 recurrence warps (thread pair per row, f32x2-packed FMAs) synced by a
// named barrier (bar.sync 1,128). A 5th fc/readout warp is fully decoupled:
// it consumes h vectors from a 32-entry smem ring via acquire/release
// counters, so its 5-level shfl reduction + sigmoids are OFF the serial
// recurrence critical path.

#define BATCH 128
#define SEQ   8000
#define HID   64
#define CHUNK 800
#define NCHUNK (SEQ / CHUNK)
#define NTHREADS 160
#define RING  32

typedef unsigned long long ull;

__device__ __forceinline__ ull ffma2(ull a, ull b, ull c) {
    ull d;
    asm("fma.rn.f32x2 %0, %1, %2, %3;" : "=l"(d) : "l"(a), "l"(b), "l"(c));
    return d;
}
__device__ __forceinline__ ull fadd2(ull a, ull b) {
    ull d;
    asm("add.rn.f32x2 %0, %1, %2;" : "=l"(d) : "l"(a), "l"(b));
    return d;
}
__device__ __forceinline__ float lo32(ull a) { return __int_as_float((unsigned)a); }
__device__ __forceinline__ float hi32(ull a) { return __int_as_float((unsigned)(a >> 32)); }

__device__ __forceinline__ unsigned ld_acq(const unsigned* p) {
    unsigned v;
    asm volatile("ld.acquire.cta.u32 %0, [%1];" : "=r"(v) : "l"(p) : "memory");
    return v;
}
__device__ __forceinline__ void st_rel(unsigned* p, unsigned v) {
    asm volatile("st.release.cta.u32 [%0], %1;" :: "l"(p), "r"(v) : "memory");
}
__device__ __forceinline__ void barrier_rec() {
    asm volatile("bar.sync 1, 128;" ::: "memory");
}

__device__ __forceinline__ float tanh_fast(float z) {
    float e = __expf(2.0f * z);
    return 1.0f - __fdividef(2.0f, e + 1.0f);
}
__device__ __forceinline__ float sigmoid_fast(float z) {
    return __fdividef(1.0f, 1.0f + __expf(-z));
}

__global__ void __launch_bounds__(NTHREADS, 1)
rnn_kernel(const float* __restrict__ x,      // [B, S]
           const float* __restrict__ W_ih,   // [H, 1]
           const float* __restrict__ b_ih,   // [H]
           const float* __restrict__ W_hh,   // [H, H]
           const float* __restrict__ b_hh,   // [H]
           const float* __restrict__ fc_w,   // [2, H]
           const float* __restrict__ fc_b,   // [2]
           float* __restrict__ out)          // [B]
{
    __shared__ __align__(16) float ring[RING][HID];  // h history ring
    __shared__ float xs[CHUNK];
    __shared__ unsigned pub;    // rec -> fc: steps produced
    __shared__ unsigned cons;   // fc -> rec: steps consumed

    const int b    = blockIdx.x;
    const int tid  = threadIdx.x;
    const int lane = tid & 31;
    const bool rec = (tid < 128);
    const int r    = tid >> 1;    // row 0..63 (rec threads)
    const int half = tid & 1;     // which 32-wide half of h

    if (tid == 0) { pub = 0; cons = 0; }
    if (tid < HID) ring[0][tid] = 0.0f;   // h_0 = 0 in slot 0
    __syncthreads();

    if (rec) {
        // ---- recurrence warps (tid 0..127) ----
        ull w2[16];               // 32 weights as 16 packed f32x2
        const double* wp = (const double*)(W_hh + r * HID + half * 32);
        #pragma unroll
        for (int i = 0; i < 16; i++) w2[i] = __double_as_longlong(wp[i]);
        const float wih_r  = W_ih[r];
        const float bias_r = b_ih[r] + b_hh[r];

        const float* xb = x + (long)b * SEQ;
        int t = 1;
        for (int c = 0; c < NCHUNK; ++c) {
            for (int i = tid; i < CHUNK; i += 128)
                xs[i] = xb[c * CHUNK + i];
            barrier_rec();

            for (int s = 0; s < CHUNK; ++s, ++t) {
                if ((t & 7) == 1) {
                    // after the bar ending step t-1, all stores <= t-1 are ordered
                    if (tid == 0)  st_rel(&pub, (unsigned)(t - 1));
                    if (tid == 32) {   // overwrite guard (slack: 24 steps, ~never spins)
                        while ((int)ld_acq(&cons) < t - 24) __nanosleep(32);
                    }
                }

                const float init = (half == 0) ? fmaf(xs[s], wih_r, bias_r) : 0.0f;

                const double2* h2 = (const double2*)(&ring[(t - 1) & (RING - 1)][half * 32]);
                ull a0 = 0ull, a1 = 0ull, a2 = 0ull, a3 = 0ull;
                #pragma unroll
                for (int i = 0; i < 4; i++) {
                    double2 hva = h2[2 * i];
                    double2 hvb = h2[2 * i + 1];
                    a0 = ffma2(w2[4 * i + 0], __double_as_longlong(hva.x), a0);
                    a1 = ffma2(w2[4 * i + 1], __double_as_longlong(hva.y), a1);
                    a2 = ffma2(w2[4 * i + 2], __double_as_longlong(hvb.x), a2);
                    a3 = ffma2(w2[4 * i + 3], __double_as_longlong(hvb.y), a3);
                }
                ull sA = fadd2(fadd2(a0, a1), fadd2(a2, a3));
                float sum = lo32(sA) + hi32(sA) + init;

                float oth = __shfl_xor_sync(0xffffffffu, sum, 1);
                float hn  = tanh_fast(sum + oth);
                if (half == 0) ring[t & (RING - 1)][r] = hn;
                barrier_rec();
            }
        }
        if (tid == 0) st_rel(&pub, (unsigned)SEQ);
    } else {
        // ---- fc/readout warp (tid 128..159), fully decoupled ----
        const float f0a = fc_w[lane];       const float f0b = fc_w[32 + lane];
        const float f1a = fc_w[64 + lane];  const float f1b = fc_w[96 + lane];
        const float fb0 = fc_b[0];          const float fb1 = fc_b[1];

        float num = 0.0f, den = 0.0f;
        for (int k = 8; k <= SEQ; k += 8) {
            while (ld_acq(&pub) < (unsigned)k) __nanosleep(64);
            #pragma unroll
            for (int j = 0; j < 8; j++) {
                const int u = k - 7 + j;                 // steps 1..SEQ
                const float* hr = ring[u & (RING - 1)];
                float hA = hr[lane];
                float hB = hr[32 + lane];
                float p0 = fmaf(f0a, hA, f0b * hB);
                float p1 = fmaf(f1a, hA, f1b * hB);
                #pragma unroll
                for (int o = 16; o > 0; o >>= 1) {
                    p0 += __shfl_xor_sync(0xffffffffu, p0, o);
                    p1 += __shfl_xor_sync(0xffffffffu, p1, o);
                }
                float sel = sigmoid_fast(p0 + fb0);
                float sc  = sigmoid_fast(p1 + fb1);
                den += sel;
                num += sc * sel;
            }
            __syncwarp();
            if (lane == 0) st_rel(&cons, (unsigned)k);
        }
        if (lane == 0) out[b] = __fdividef(num, den);
    }
}

extern "C" void kernel_launch(void* const* d_in, const int* in_sizes, int n_in,
                              void* d_out, int out_size) {
    const float* x    = (const float*)d_in[0];
    const float* W_ih = (const float*)d_in[1];
    const float* b_ih = (const float*)d_in[2];
    const float* W_hh = (const float*)d_in[3];
    const float* b_hh = (const float*)d_in[4];
    const float* fc_w = (const float*)d_in[5];
    const float* fc_b = (const float*)d_in[6];
    float* out = (float*)d_out;
    (void)in_sizes; (void)n_in; (void)out_size;

    rnn_kernel<<<BATCH, NTHREADS>>>(x, W_ih, b_ih, W_hh, b_hh, fc_w, fc_b, out);
}

// round 3
// speedup vs baseline: 1.1344x; 1.1344x over previous
#include <cuda_runtime.h>

// BasicRNN B=128, S=8000, H=64 — two-phase:
//  phase1: pure recurrence, one block/batch, 128 thr (2 per row). Streams
//          pre-activations z_t to global scratch (off the critical path).
//  phase2: parallel readout: tanh(z) -> fc -> sigmoid -> weighted mean over t.

#define BATCH 128
#define SEQ   8000
#define HID   64
#define CHUNK 1600
#define NCHUNK (SEQ / CHUNK)

typedef unsigned long long ull;

// 128*8000*64 floats = 262 MB scratch for pre-activations z
__device__ float g_z[(size_t)BATCH * SEQ * HID];

__device__ __forceinline__ ull ffma2(ull a, ull b, ull c) {
    ull d;
    asm("fma.rn.f32x2 %0, %1, %2, %3;" : "=l"(d) : "l"(a), "l"(b), "l"(c));
    return d;
}
__device__ __forceinline__ ull fadd2(ull a, ull b) {
    ull d;
    asm("add.rn.f32x2 %0, %1, %2;" : "=l"(d) : "l"(a), "l"(b));
    return d;
}
__device__ __forceinline__ float lo32(ull a) { return __int_as_float((unsigned)a); }
__device__ __forceinline__ float hi32(ull a) { return __int_as_float((unsigned)(a >> 32)); }

__device__ __forceinline__ float tanh_fast(float z) {
    // 1 - 2/(exp(2z)+1), ex2+rcp based (~1e-6 abs err)
    float e;
    asm("ex2.approx.f32 %0, %1;" : "=f"(e) : "f"(z * 2.8853900817779268f));
    float rcp;
    asm("rcp.approx.f32 %0, %1;" : "=f"(rcp) : "f"(e + 1.0f));
    return fmaf(-2.0f, rcp, 1.0f);
}
__device__ __forceinline__ float sigmoid_fast(float z) {
    float e;
    asm("ex2.approx.f32 %0, %1;" : "=f"(e) : "f"(z * -1.4426950408889634f));
    float rcp;
    asm("rcp.approx.f32 %0, %1;" : "=f"(rcp) : "f"(e + 1.0f));
    return rcp;
}

// ---------------- phase 1: recurrence ----------------
__global__ void __launch_bounds__(128, 1)
rnn_phase1(const float* __restrict__ x,      // [B, S]
           const float* __restrict__ W_ih,   // [H, 1]
           const float* __restrict__ b_ih,   // [H]
           const float* __restrict__ W_hh,   // [H, H]
           const float* __restrict__ b_hh)   // [H]
{
    __shared__ __align__(16) float hb[2][HID];
    __shared__ float xs[CHUNK];

    const int b    = blockIdx.x;
    const int tid  = threadIdx.x;
    const int r    = tid >> 1;   // row 0..63
    const int half = tid & 1;    // which 32-wide half of h this lane covers

    // weights for my (row, half): 32 floats as 16 packed f32x2
    ull w2[16];
    {
        const double* wp = (const double*)(W_hh + r * HID + half * 32);
        #pragma unroll
        for (int i = 0; i < 16; i++) w2[i] = __double_as_longlong(wp[i]);
    }
    const float wih_r  = W_ih[r];
    const float bias_r = b_ih[r] + b_hh[r];

    if (tid < HID) hb[0][tid] = 0.0f;  // h_0

    const float* xb = x + (long)b * SEQ;
    float* zrow = g_z + (size_t)b * SEQ * HID;   // advances by HID per step

    __syncthreads();

    for (int c = 0; c < NCHUNK; ++c) {
        for (int i = tid; i < CHUNK; i += 128)
            xs[i] = xb[c * CHUNK + i];
        __syncthreads();

        #pragma unroll 1
        for (int s = 0; s < CHUNK; s += 2) {
            // ---- step A: hb[0] -> hb[1] ----
            #pragma unroll
            for (int u = 0; u < 2; ++u) {
                const float* hsrc = hb[u];
                float*       hdst = hb[u ^ 1];
                const float  init = (half == 0) ? fmaf(xs[s + u], wih_r, bias_r) : 0.0f;

                const double2* h2 = (const double2*)(hsrc + half * 32);
                ull a0 = 0ull, a1 = 0ull, a2 = 0ull, a3 = 0ull;
                #pragma unroll
                for (int i = 0; i < 4; i++) {
                    double2 hva = h2[2 * i];
                    double2 hvb = h2[2 * i + 1];
                    a0 = ffma2(w2[4 * i + 0], __double_as_longlong(hva.x), a0);
                    a1 = ffma2(w2[4 * i + 1], __double_as_longlong(hva.y), a1);
                    a2 = ffma2(w2[4 * i + 2], __double_as_longlong(hvb.x), a2);
                    a3 = ffma2(w2[4 * i + 3], __double_as_longlong(hvb.y), a3);
                }
                ull sA = fadd2(fadd2(a0, a1), fadd2(a2, a3));
                float sum = lo32(sA) + hi32(sA) + init;
                float z   = sum + __shfl_xor_sync(0xffffffffu, sum, 1);

                if (half == 0) {
                    zrow[r] = z;              // STG: fire-and-forget, pre-tanh
                    hdst[r] = tanh_fast(z);   // STS for next step
                }
                zrow += HID;
                __syncthreads();
            }
        }
    }
}

// ---------------- phase 2: parallel readout ----------------
__global__ void __launch_bounds__(256, 1)
rnn_phase2(const float* __restrict__ fc_w,   // [2, H]
           const float* __restrict__ fc_b,   // [2]
           float* __restrict__ out)          // [B]
{
    __shared__ float snum[8], sden[8];

    const int b    = blockIdx.x;
    const int w    = threadIdx.x >> 5;
    const int lane = threadIdx.x & 31;

    const float f0a = fc_w[lane];       const float f0b = fc_w[32 + lane];
    const float f1a = fc_w[64 + lane];  const float f1b = fc_w[96 + lane];
    const float fb0 = fc_b[0];          const float fb1 = fc_b[1];

    const float* zb = g_z + (size_t)b * SEQ * HID;

    float num = 0.0f, den = 0.0f;
    for (int t = w; t < SEQ; t += 8) {
        const float* zr = zb + (size_t)t * HID;
        float hA = tanh_fast(zr[lane]);
        float hB = tanh_fast(zr[32 + lane]);
        float p0 = fmaf(f0a, hA, f0b * hB);
        float p1 = fmaf(f1a, hA, f1b * hB);
        #pragma unroll
        for (int o = 16; o > 0; o >>= 1) {
            p0 += __shfl_xor_sync(0xffffffffu, p0, o);
            p1 += __shfl_xor_sync(0xffffffffu, p1, o);
        }
        float sel = sigmoid_fast(p0 + fb0);
        float sc  = sigmoid_fast(p1 + fb1);
        den += sel;
        num += sc * sel;
    }
    if (lane == 0) { snum[w] = num; sden[w] = den; }
    __syncthreads();
    if (threadIdx.x == 0) {
        float N = 0.0f, D = 0.0f;
        #pragma unroll
        for (int i = 0; i < 8; i++) { N += snum[i]; D += sden[i]; }
        out[b] = __fdividef(N, D);
    }
}

extern "C" void kernel_launch(void* const* d_in, const int* in_sizes, int n_in,
                              void* d_out, int out_size) {
    const float* x    = (const float*)d_in[0];
    const float* W_ih = (const float*)d_in[1];
    const float* b_ih = (const float*)d_in[2];
    const float* W_hh = (const float*)d_in[3];
    const float* b_hh = (const float*)d_in[4];
    const float* fc_w = (const float*)d_in[5];
    const float* fc_b = (const float*)d_in[6];
    float* out = (float*)d_out;
    (void)in_sizes; (void)n_in; (void)out_size;

    rnn_phase1<<<BATCH, 128>>>(x, W_ih, b_ih, W_hh, b_hh);
    rnn_phase2<<<BATCH, 256>>>(fc_w, fc_b, out);
}

// round 4
// speedup vs baseline: 1.9436x; 1.7133x over previous
#include <cuda_runtime.h>

// BasicRNN B=128, S=8000, H=64 — two-phase:
//  phase1: pure recurrence. 64 threads/block (one row per thread, 2 warps).
//          Broadcast LDS of h, 32 packed f32x2 FMAs into 8 accumulators,
//          streams pre-activations z_t to global scratch (off critical path).
//  phase2: massively parallel readout (1024 blocks), deterministic 2-stage sum.

#define BATCH 128
#define SEQ   8000
#define HID   64
#define CHUNK 1600
#define NCHUNK (SEQ / CHUNK)
#define NCHK2 8                 // phase2 seq chunks per batch
#define TCHK  (SEQ / NCHK2)     // 1000 timesteps per phase2 block

typedef unsigned long long ull;

// 128*8000*64 floats = 262 MB scratch for pre-activations z
__device__ float g_z[(size_t)BATCH * SEQ * HID];
__device__ float g_pnum[BATCH * NCHK2];
__device__ float g_pden[BATCH * NCHK2];

__device__ __forceinline__ ull ffma2(ull a, ull b, ull c) {
    ull d;
    asm("fma.rn.f32x2 %0, %1, %2, %3;" : "=l"(d) : "l"(a), "l"(b), "l"(c));
    return d;
}
__device__ __forceinline__ ull fadd2(ull a, ull b) {
    ull d;
    asm("add.rn.f32x2 %0, %1, %2;" : "=l"(d) : "l"(a), "l"(b));
    return d;
}
__device__ __forceinline__ float lo32(ull a) { return __int_as_float((unsigned)a); }
__device__ __forceinline__ float hi32(ull a) { return __int_as_float((unsigned)(a >> 32)); }

__device__ __forceinline__ float tanh_fast(float z) {
    // 1 - 2/(exp(2z)+1), ex2+rcp based (~1e-6 abs err)
    float e;
    asm("ex2.approx.f32 %0, %1;" : "=f"(e) : "f"(z * 2.8853900817779268f));
    float rcp;
    asm("rcp.approx.f32 %0, %1;" : "=f"(rcp) : "f"(e + 1.0f));
    return fmaf(-2.0f, rcp, 1.0f);
}
__device__ __forceinline__ float sigmoid_fast(float z) {
    float e;
    asm("ex2.approx.f32 %0, %1;" : "=f"(e) : "f"(z * -1.4426950408889634f));
    float rcp;
    asm("rcp.approx.f32 %0, %1;" : "=f"(rcp) : "f"(e + 1.0f));
    return rcp;
}

// ---------------- phase 1: recurrence (64 threads, 1 row/thread) ----------------
__global__ void __launch_bounds__(64, 1)
rnn_phase1(const float* __restrict__ x,      // [B, S]
           const float* __restrict__ W_ih,   // [H, 1]
           const float* __restrict__ b_ih,   // [H]
           const float* __restrict__ W_hh,   // [H, H]
           const float* __restrict__ b_hh)   // [H]
{
    __shared__ __align__(16) float hb[2][HID];
    __shared__ float xs[CHUNK];

    const int b = blockIdx.x;
    const int r = threadIdx.x;   // row 0..63

    // full row of W_hh: 64 floats as 32 packed f32x2 (64 regs)
    ull w2[32];
    {
        const double* wp = (const double*)(W_hh + r * HID);
        #pragma unroll
        for (int i = 0; i < 32; i++) w2[i] = __double_as_longlong(wp[i]);
    }
    const float wih_r  = W_ih[r];
    const float bias_r = b_ih[r] + b_hh[r];

    hb[0][r] = 0.0f;   // h_0

    const float* xb = x + (long)b * SEQ;
    float* zrow = g_z + (size_t)b * SEQ * HID;

    __syncthreads();

    for (int c = 0; c < NCHUNK; ++c) {
        for (int i = r; i < CHUNK; i += 64)
            xs[i] = xb[c * CHUNK + i];
        __syncthreads();

        #pragma unroll 1
        for (int s = 0; s < CHUNK; s += 2) {
            #pragma unroll
            for (int u = 0; u < 2; ++u) {
                const float* hsrc = hb[u];
                float*       hdst = hb[u ^ 1];
                const float  xp   = fmaf(xs[s + u], wih_r, bias_r);

                // broadcast loads: every lane reads the same h chunk (N=1)
                const double2* h2 = (const double2*)hsrc;   // 16 x double2 = 64 floats
                ull a[8];
                #pragma unroll
                for (int i = 0; i < 8; i++) a[i] = 0ull;
                #pragma unroll
                for (int i = 0; i < 16; i++) {
                    double2 v = h2[i];
                    a[(2 * i)     & 7] = ffma2(w2[2 * i],     __double_as_longlong(v.x), a[(2 * i)     & 7]);
                    a[(2 * i + 1) & 7] = ffma2(w2[2 * i + 1], __double_as_longlong(v.y), a[(2 * i + 1) & 7]);
                }
                ull t0 = fadd2(fadd2(a[0], a[1]), fadd2(a[2], a[3]));
                ull t1 = fadd2(fadd2(a[4], a[5]), fadd2(a[6], a[7]));
                ull tS = fadd2(t0, t1);
                float z = lo32(tS) + hi32(tS) + xp;

                zrow[r] = z;              // STG pre-tanh: fire-and-forget
                hdst[r] = tanh_fast(z);   // STS for next step
                zrow += HID;
                __syncthreads();
            }
        }
    }
}

// ---------------- phase 2: parallel readout (1024 blocks) ----------------
__global__ void __launch_bounds__(256, 1)
rnn_phase2(const float* __restrict__ fc_w,   // [2, H]
           const float* __restrict__ fc_b)   // [2]
{
    __shared__ float snum[8], sden[8];

    const int b    = blockIdx.x >> 3;        // batch
    const int ck   = blockIdx.x & 7;         // seq chunk
    const int w    = threadIdx.x >> 5;
    const int lane = threadIdx.x & 31;

    const float f0a = fc_w[lane];       const float f0b = fc_w[32 + lane];
    const float f1a = fc_w[64 + lane];  const float f1b = fc_w[96 + lane];
    const float fb0 = fc_b[0];          const float fb1 = fc_b[1];

    const float* zb = g_z + (size_t)b * SEQ * HID + (size_t)ck * TCHK * HID
                          + (size_t)w * (TCHK / 8) * HID;

    float num = 0.0f, den = 0.0f;
    #pragma unroll 4
    for (int i = 0; i < TCHK / 8; ++i) {     // 125 timesteps per warp
        const float* zr = zb + (size_t)i * HID;
        float hA = tanh_fast(zr[lane]);
        float hB = tanh_fast(zr[32 + lane]);
        float p0 = fmaf(f0a, hA, f0b * hB);
        float p1 = fmaf(f1a, hA, f1b * hB);
        #pragma unroll
        for (int o = 16; o > 0; o >>= 1) {
            p0 += __shfl_xor_sync(0xffffffffu, p0, o);
            p1 += __shfl_xor_sync(0xffffffffu, p1, o);
        }
        float sel = sigmoid_fast(p0 + fb0);
        float sc  = sigmoid_fast(p1 + fb1);
        den += sel;
        num += sc * sel;
    }
    if (lane == 0) { snum[w] = num; sden[w] = den; }
    __syncthreads();
    if (threadIdx.x == 0) {
        float N = 0.0f, D = 0.0f;
        #pragma unroll
        for (int i = 0; i < 8; i++) { N += snum[i]; D += sden[i]; }
        g_pnum[b * NCHK2 + ck] = N;
        g_pden[b * NCHK2 + ck] = D;
    }
}

// ---------------- phase 3: deterministic final reduce ----------------
__global__ void rnn_finish(float* __restrict__ out) {
    const int b = threadIdx.x;
    float N = 0.0f, D = 0.0f;
    #pragma unroll
    for (int i = 0; i < NCHK2; i++) {
        N += g_pnum[b * NCHK2 + i];
        D += g_pden[b * NCHK2 + i];
    }
    out[b] = __fdividef(N, D);
}

extern "C" void kernel_launch(void* const* d_in, const int* in_sizes, int n_in,
                              void* d_out, int out_size) {
    const float* x    = (const float*)d_in[0];
    const float* W_ih = (const float*)d_in[1];
    const float* b_ih = (const float*)d_in[2];
    const float* W_hh = (const float*)d_in[3];
    const float* b_hh = (const float*)d_in[4];
    const float* fc_w = (const float*)d_in[5];
    const float* fc_b = (const float*)d_in[6];
    float* out = (float*)d_out;
    (void)in_sizes; (void)n_in; (void)out_size;

    rnn_phase1<<<BATCH, 64>>>(x, W_ih, b_ih, W_hh, b_hh);
    rnn_phase2<<<BATCH * NCHK2, 256>>>(fc_w, fc_b);
    rnn_finish<<<1, BATCH>>>(out);
}

// round 5
// speedup vs baseline: 2.4659x; 1.2687x over previous
#include <cuda_runtime.h>

// BasicRNN B=128, S=8000, H=64 — two-phase:
//  phase1: pure recurrence. 64 threads/block (one row per thread, 2 warps).
//          MUFU.TANH on the critical path, z streamed to scratch as one
//          STG.128 per 4 steps in [b][t/4][row][4] layout.
//  phase2: parallel readout, 4 timesteps/iter via float4 loads, 1280 blocks.

#define BATCH 128
#define SEQ   8000
#define HID   64
#define CHUNK 1600
#define NCHUNK (SEQ / CHUNK)
#define GROUPS (SEQ / 4)        // 2000 groups of 4 timesteps
#define NCHK2 10                // phase2 chunks per batch
#define GCHK  (GROUPS / NCHK2)  // 200 groups per phase2 block
#define GWARP (GCHK / 8)        // 25 groups per warp

typedef unsigned long long ull;

// z scratch: [B][GROUPS][HID][4] = 262 MB
__device__ float g_z[(size_t)BATCH * GROUPS * HID * 4];
__device__ float g_pnum[BATCH * NCHK2];
__device__ float g_pden[BATCH * NCHK2];

__device__ __forceinline__ ull ffma2(ull a, ull b, ull c) {
    ull d;
    asm("fma.rn.f32x2 %0, %1, %2, %3;" : "=l"(d) : "l"(a), "l"(b), "l"(c));
    return d;
}
__device__ __forceinline__ ull fadd2(ull a, ull b) {
    ull d;
    asm("add.rn.f32x2 %0, %1, %2;" : "=l"(d) : "l"(a), "l"(b));
    return d;
}
__device__ __forceinline__ float lo32(ull a) { return __int_as_float((unsigned)a); }
__device__ __forceinline__ float hi32(ull a) { return __int_as_float((unsigned)(a >> 32)); }
__device__ __forceinline__ ull pack2(float lo, float hi) {
    return (ull)__float_as_uint(lo) | ((ull)__float_as_uint(hi) << 32);
}

__device__ __forceinline__ float tanh_hw(float z) {        // MUFU.TANH, 16 cyc
    float r;
    asm("tanh.approx.f32 %0, %1;" : "=f"(r) : "f"(z));
    return r;
}
__device__ __forceinline__ float tanh_prec(float z) {      // ~1e-6 abs err
    float e;
    asm("ex2.approx.f32 %0, %1;" : "=f"(e) : "f"(z * 2.8853900817779268f));
    float rcp;
    asm("rcp.approx.f32 %0, %1;" : "=f"(rcp) : "f"(e + 1.0f));
    return fmaf(-2.0f, rcp, 1.0f);
}
__device__ __forceinline__ float sigmoid_fast(float z) {
    float e;
    asm("ex2.approx.f32 %0, %1;" : "=f"(e) : "f"(z * -1.4426950408889634f));
    float rcp;
    asm("rcp.approx.f32 %0, %1;" : "=f"(rcp) : "f"(e + 1.0f));
    return rcp;
}

// ---------------- phase 1: recurrence ----------------
__global__ void __launch_bounds__(64, 1)
rnn_phase1(const float* __restrict__ x,      // [B, S]
           const float* __restrict__ W_ih,   // [H, 1]
           const float* __restrict__ b_ih,   // [H]
           const float* __restrict__ W_hh,   // [H, H]
           const float* __restrict__ b_hh)   // [H]
{
    __shared__ __align__(16) float hb[2][HID];
    __shared__ float xs[CHUNK];

    const int b = blockIdx.x;
    const int r = threadIdx.x;   // row 0..63

    ull w2[32];                  // full W_hh row, packed
    {
        const double* wp = (const double*)(W_hh + r * HID);
        #pragma unroll
        for (int i = 0; i < 32; i++) w2[i] = __double_as_longlong(wp[i]);
    }
    const float wih_r  = W_ih[r];
    const float bias_r = b_ih[r] + b_hh[r];

    hb[0][r] = 0.0f;   // h_0

    const float* xb = x + (long)b * SEQ;
    float4* zp = (float4*)(g_z + (size_t)b * GROUPS * HID * 4) + r;  // [g][r] of float4

    __syncthreads();

    for (int c = 0; c < NCHUNK; ++c) {
        for (int i = r; i < CHUNK; i += 64)
            xs[i] = xb[c * CHUNK + i];
        __syncthreads();

        #pragma unroll 1
        for (int s = 0; s < CHUNK; s += 4) {
            float zq[4];
            #pragma unroll
            for (int u = 0; u < 4; ++u) {
                const float* hsrc = hb[u & 1];
                float*       hdst = hb[(u & 1) ^ 1];
                const float  xp   = fmaf(xs[s + u], wih_r, bias_r);

                const double2* h2 = (const double2*)hsrc;
                ull a[8];
                a[0] = pack2(xp, 0.0f);
                #pragma unroll
                for (int i = 1; i < 8; i++) a[i] = 0ull;
                #pragma unroll
                for (int i = 0; i < 16; i++) {
                    double2 v = h2[i];
                    a[(2 * i)     & 7] = ffma2(w2[2 * i],     __double_as_longlong(v.x), a[(2 * i)     & 7]);
                    a[(2 * i + 1) & 7] = ffma2(w2[2 * i + 1], __double_as_longlong(v.y), a[(2 * i + 1) & 7]);
                }
                ull t0 = fadd2(fadd2(a[0], a[1]), fadd2(a[2], a[3]));
                ull t1 = fadd2(fadd2(a[4], a[5]), fadd2(a[6], a[7]));
                ull tS = fadd2(t0, t1);
                float z = lo32(tS) + hi32(tS);

                zq[u]   = z;
                hdst[r] = tanh_hw(z);
                __syncthreads();
            }
            *zp = make_float4(zq[0], zq[1], zq[2], zq[3]);  // fire-and-forget
            zp += HID;
        }
    }
}

// ---------------- phase 2: parallel readout (1280 blocks) ----------------
__global__ void __launch_bounds__(256, 1)
rnn_phase2(const float* __restrict__ fc_w,   // [2, H]
           const float* __restrict__ fc_b)   // [2]
{
    __shared__ float snum[8], sden[8];

    const int bk   = blockIdx.x;
    const int b    = bk / NCHK2;             // batch
    const int ck   = bk % NCHK2;             // seq chunk
    const int w    = threadIdx.x >> 5;
    const int lane = threadIdx.x & 31;

    const float f0a = fc_w[lane];       const float f0b = fc_w[32 + lane];
    const float f1a = fc_w[64 + lane];  const float f1b = fc_w[96 + lane];
    const float fb0 = fc_b[0];          const float fb1 = fc_b[1];

    // base group for this warp
    const float4* zb = (const float4*)(g_z +
        ((size_t)b * GROUPS + (size_t)ck * GCHK + (size_t)w * GWARP) * HID * 4);

    float num = 0.0f, den = 0.0f;
    #pragma unroll 1
    for (int i = 0; i < GWARP; ++i) {        // 25 groups = 100 timesteps
        const float4* zg = zb + (size_t)i * HID;
        float4 zA = zg[lane];                // rows 0..31, 4 steps
        float4 zB = zg[32 + lane];           // rows 32..63, 4 steps
        float p0[4], p1[4];
        {
            float a, bb;
            a = tanh_prec(zA.x); bb = tanh_prec(zB.x);
            p0[0] = fmaf(f0a, a, f0b * bb); p1[0] = fmaf(f1a, a, f1b * bb);
            a = tanh_prec(zA.y); bb = tanh_prec(zB.y);
            p0[1] = fmaf(f0a, a, f0b * bb); p1[1] = fmaf(f1a, a, f1b * bb);
            a = tanh_prec(zA.z); bb = tanh_prec(zB.z);
            p0[2] = fmaf(f0a, a, f0b * bb); p1[2] = fmaf(f1a, a, f1b * bb);
            a = tanh_prec(zA.w); bb = tanh_prec(zB.w);
            p0[3] = fmaf(f0a, a, f0b * bb); p1[3] = fmaf(f1a, a, f1b * bb);
        }
        #pragma unroll
        for (int o = 16; o > 0; o >>= 1) {
            #pragma unroll
            for (int j = 0; j < 4; j++) {
                p0[j] += __shfl_xor_sync(0xffffffffu, p0[j], o);
                p1[j] += __shfl_xor_sync(0xffffffffu, p1[j], o);
            }
        }
        #pragma unroll
        for (int j = 0; j < 4; j++) {
            float sel = sigmoid_fast(p0[j] + fb0);
            float sc  = sigmoid_fast(p1[j] + fb1);
            den += sel;
            num += sc * sel;
        }
    }
    if (lane == 0) { snum[w] = num; sden[w] = den; }
    __syncthreads();
    if (threadIdx.x == 0) {
        float N = 0.0f, D = 0.0f;
        #pragma unroll
        for (int i = 0; i < 8; i++) { N += snum[i]; D += sden[i]; }
        g_pnum[b * NCHK2 + ck] = N;
        g_pden[b * NCHK2 + ck] = D;
    }
}

// ---------------- phase 3: deterministic final reduce ----------------
__global__ void rnn_finish(float* __restrict__ out) {
    const int b = threadIdx.x;
    float N = 0.0f, D = 0.0f;
    #pragma unroll
    for (int i = 0; i < NCHK2; i++) {
        N += g_pnum[b * NCHK2 + i];
        D += g_pden[b * NCHK2 + i];
    }
    out[b] = __fdividef(N, D);
}

extern "C" void kernel_launch(void* const* d_in, const int* in_sizes, int n_in,
                              void* d_out, int out_size) {
    const float* x    = (const float*)d_in[0];
    const float* W_ih = (const float*)d_in[1];
    const float* b_ih = (const float*)d_in[2];
    const float* W_hh = (const float*)d_in[3];
    const float* b_hh = (const float*)d_in[4];
    const float* fc_w = (const float*)d_in[5];
    const float* fc_b = (const float*)d_in[6];
    float* out = (float*)d_out;
    (void)in_sizes; (void)n_in; (void)out_size;

    rnn_phase1<<<BATCH, 64>>>(x, W_ih, b_ih, W_hh, b_hh);
    rnn_phase2<<<BATCH * NCHK2, 256>>>(fc_w, fc_b);
    rnn_finish<<<1, BATCH>>>(out);
}